// round 15
// baseline (speedup 1.0000x reference)
#include <cuda_runtime.h>
#include <math.h>

// RandomElasticDeformation3D — staged-f32 flow pipeline (bit-identical chains):
//   K1 weights | K2 resizeD+resizeH | K3 resizeW+gaussD (d-chunked)
//   K4 gaussH(smem ring)+gaussW+warp fused
// All fma chains and per-stage f32 roundings unchanged => same output bits.

#define DV 128
#define NVOX (DV * DV * DV)
#define IMG_FLOATS_PER_B (NVOX * 4)
#define ROWF (DV * 3)

static __device__ float4 g_A[DV];           // cubic resize rows (128 x 4)
static __device__ float  g_G[16];           // gaussian taps
static __device__ float  g_RH[2 * DV * DV * 4 * 3];          // [b,d,h,k,c]
static __device__ float  g_F1[(size_t)2 * DV * DV * DV * 3]; // after gauss D

// ---------------------------------------------------------------------------
__device__ __forceinline__ float keys_cubic_f32(float x) {
    float o = __fadd_rn(__fmul_rn(__fmul_rn(__fadd_rn(__fmul_rn(1.5f, x), -2.5f), x), x), 1.0f);
    if (x >= 1.0f)
        o = __fadd_rn(__fmul_rn(__fadd_rn(__fmul_rn(__fadd_rn(__fmul_rn(-0.5f, x), 2.5f), x), -4.0f), x), 2.0f);
    if (x >= 2.0f) o = 0.0f;
    return o;
}

__global__ void precompute_weights_kernel() {
    const int n = threadIdx.x;
    if (n < 16) {
        double ks = 0.0;
        for (int t = 0; t < 16; ++t) {
            double ax = (double)(t - 7);
            ks += exp(-ax * ax / 12.5);
        }
        double axn = (double)(n - 7);
        g_G[n] = (float)(exp(-axn * axn / 12.5) / ks);
    }
    if (n < DV) {
        float s = __fadd_rn(__fmul_rn(__fadd_rn((float)n, 0.5f), 0.03125f), -0.5f);
        float wv[4];
#pragma unroll
        for (int i = 0; i < 4; ++i) wv[i] = keys_cubic_f32(fabsf(__fadd_rn(s, -(float)i)));
        float tot = __fadd_rn(__fadd_rn(__fadd_rn(wv[0], wv[1]), wv[2]), wv[3]);
        g_A[n] = make_float4(__fdiv_rn(wv[0], tot), __fdiv_rn(wv[1], tot),
                             __fdiv_rn(wv[2], tot), __fdiv_rn(wv[3], tot));
    }
}

// ---------------------------------------------------------------------------
// K2: resize D then H.  grid(d, b), 128 threads (h).
// ---------------------------------------------------------------------------
__global__ void __launch_bounds__(128)
resizeDH_kernel(const float* __restrict__ coarse) {
    const int h = threadIdx.x;
    const int d = blockIdx.x;
    const int b = blockIdx.y;

    __shared__ float sRD[48];               // [j,k,c]
    if (threadIdx.x < 48) {
        const int c = threadIdx.x % 3;
        const int k = (threadIdx.x / 3) % 4;
        const int j = threadIdx.x / 12;
        const float4 A = g_A[d];
        const float Ai[4] = {A.x, A.y, A.z, A.w};
        float acc = 0.0f;
#pragma unroll
        for (int i = 0; i < 4; ++i)
            acc = fmaf(Ai[i], coarse[(((b * 4 + i) * 4 + j) * 4 + k) * 3 + c], acc);
        sRD[threadIdx.x] = acc;
    }
    __syncthreads();

    const float4 A = g_A[h];
    const float Aj[4] = {A.x, A.y, A.z, A.w};
    float* o = g_RH + ((b * DV + d) * DV + h) * 12;
#pragma unroll
    for (int r = 0; r < 12; ++r) {
        float acc = 0.0f;
#pragma unroll
        for (int j = 0; j < 4; ++j)
            acc = fmaf(Aj[j], sRD[j * 12 + r], acc);
        o[r] = acc;
    }
}

// ---------------------------------------------------------------------------
// K3: resize W + gauss D fused, d-chunked.  grid(h, 4, b), 128 thr (w).
// ---------------------------------------------------------------------------
#define D_CHUNK 32
__global__ void __launch_bounds__(128)
resizeW_gaussD_kernel() {
    const int w = threadIdx.x;
    const int h = blockIdx.x;
    const int d0 = blockIdx.y * D_CHUNK;
    const int b = blockIdx.z;

    __shared__ float sRH[DV * 12];          // RH[b, :, h, :, :]
    for (int t = threadIdx.x; t < DV * 12; t += 128)
        sRH[t] = g_RH[((b * DV) * DV + h) * 12 + (t / 12) * DV * 12 + (t % 12)];
    __syncthreads();

    const float4 A = g_A[w];
    const float Ak[4] = {A.x, A.y, A.z, A.w};
    float G[16];
#pragma unroll
    for (int t = 0; t < 16; ++t) G[t] = g_G[t];

    auto r3 = [&](int dp, int c) -> float {
        float acc = 0.0f;
#pragma unroll
        for (int k = 0; k < 4; ++k)
            acc = fmaf(Ak[k], sRH[dp * 12 + k * 3 + c], acc);
        return acc;
    };

    float win0[16], win1[16], win2[16];
#pragma unroll
    for (int t = 0; t < 16; ++t) {
        const int dp = d0 + t - 7;
        const bool ok = (dp >= 0) && (dp < DV);
        win0[t] = ok ? r3(dp, 0) : 0.0f;
        win1[t] = ok ? r3(dp, 1) : 0.0f;
        win2[t] = ok ? r3(dp, 2) : 0.0f;
    }

    for (int d = d0; d < d0 + D_CHUNK; ++d) {
        float a0 = 0.0f, a1 = 0.0f, a2 = 0.0f;
#pragma unroll
        for (int t = 0; t < 16; ++t) {
            a0 = fmaf(G[t], win0[t], a0);
            a1 = fmaf(G[t], win1[t], a1);
            a2 = fmaf(G[t], win2[t], a2);
        }
        float* o = g_F1 + ((size_t)b * DV * DV + (size_t)d * DV + h) * ROWF + w * 3;
        o[0] = a0; o[1] = a1; o[2] = a2;
#pragma unroll
        for (int t = 0; t < 15; ++t) { win0[t] = win0[t + 1]; win1[t] = win1[t + 1]; win2[t] = win2[t + 1]; }
        const int nxt = d + 9;
        const bool ok = (nxt < DV);
        win0[15] = ok ? r3(nxt, 0) : 0.0f;
        win1[15] = ok ? r3(nxt, 1) : 0.0f;
        win2[15] = ok ? r3(nxt, 2) : 0.0f;
    }
}

// ---------------------------------------------------------------------------
// K4: gaussH + gaussW + warp fused.  grid(H/16, d, b), 128 threads (w).
// gaussH rolling window lives in a SMEM ring (thread-private columns, no
// conflicts, no extra syncs) to free ~48 registers -> higher occupancy.
// Ring slot for h-position hp is (hp & 15); fma order stays ascending t
// over identical values => bit-identical output.
// ---------------------------------------------------------------------------
#define H_TILE 16
__global__ void __launch_bounds__(128, 8)
warp_fused_kernel(const float4* __restrict__ img,
                  const int*    __restrict__ lab,
                  float4*       __restrict__ out_img,
                  float*        __restrict__ out_lab) {
    const int w  = threadIdx.x;
    const int h0 = blockIdx.x * H_TILE;
    const int d  = blockIdx.y;
    const int b  = blockIdx.z;

    // wp = -7..136 at (wp+7)*3+c  =>  (DV+16)*3 = 432 floats.
    __shared__ float row[(DV + 16) * 3];
    // ring[slot][c][w]: gaussH window, slot = hp & 15.  24 KB.
    __shared__ float ring[16][3][DV];

    if (threadIdx.x < 21) row[threadIdx.x] = 0.0f;                 // wp = -7..-1
    if (threadIdx.x < 27) row[(DV + 7) * 3 + threadIdx.x] = 0.0f;  // wp = 128..136

    float G[16];
#pragma unroll
    for (int t = 0; t < 16; ++t) G[t] = g_G[t];

    // F1 element address for (b, d, hp, w, c):
    const size_t colbase = ((size_t)b * DV + d) * DV * ROWF + w * 3;

#pragma unroll
    for (int t = 0; t < 16; ++t) {
        const int hp = h0 + t - 7;
        const bool ok = (hp >= 0) && (hp < DV);
        const float* src = g_F1 + colbase + (size_t)hp * ROWF;
        const int s = hp & 15;
        ring[s][0][w] = ok ? src[0] : 0.0f;
        ring[s][1][w] = ok ? src[1] : 0.0f;
        ring[s][2][w] = ok ? src[2] : 0.0f;
    }

    const float4* ib = img + (size_t)b * NVOX;

    for (int i = 0; i < H_TILE; ++i) {
        const int h = h0 + i;

        // prefetch F1[h+9] early (consumed at end of iteration)
        float nx0 = 0.0f, nx1 = 0.0f, nx2 = 0.0f;
        {
            const int hp = h + 9;
            if (hp < DV) {
                const float* src = g_F1 + colbase + (size_t)hp * ROWF;
                nx0 = src[0]; nx1 = src[1]; nx2 = src[2];
            }
        }

        // ---- gaussH (ascending t over identical values => same bits) ----
        float f20 = 0.0f, f21 = 0.0f, f22 = 0.0f;
#pragma unroll
        for (int t = 0; t < 16; ++t) {
            const int s = (h + t - 7) & 15;
            f20 = fmaf(G[t], ring[s][0][w], f20);
            f21 = fmaf(G[t], ring[s][1][w], f21);
            f22 = fmaf(G[t], ring[s][2][w], f22);
        }

        // refill expired slot (own column only — no cross-thread hazard)
        {
            const int s = (h + 9) & 15;
            ring[s][0][w] = nx0; ring[s][1][w] = nx1; ring[s][2][w] = nx2;
        }

        row[21 + w * 3 + 0] = f20;
        row[21 + w * 3 + 1] = f21;
        row[21 + w * 3 + 2] = f22;
        __syncthreads();

        // ---- gaussW + *ALPHA (unchanged) ----
        float fl[3];
#pragma unroll
        for (int c = 0; c < 3; ++c) {
            float acc = 0.0f;
#pragma unroll
            for (int t = 0; t < 16; ++t)
                acc = fmaf(G[t], row[(w + t) * 3 + c], acc);
            fl[c] = __fmul_rn(acc, 35.0f);
        }

        const float wd = __fadd_rn((float)d, fl[0]);
        const float wh = __fadd_rn((float)h, fl[1]);
        const float ww = __fadd_rn((float)w, fl[2]);

        const float fdd = floorf(wd), fhh = floorf(wh), fww = floorf(ww);
        const float td = wd - fdd, th = wh - fhh, tw = ww - fww;

        const int d0i = min(max((int)fdd,     0), DV - 1);
        const int d1i = min(max((int)fdd + 1, 0), DV - 1);
        const int h0i = min(max((int)fhh,     0), DV - 1);
        const int h1i = min(max((int)fhh + 1, 0), DV - 1);
        const int w0i = min(max((int)fww,     0), DV - 1);
        const int w1i = min(max((int)fww + 1, 0), DV - 1);

        const float omtw = 1.0f - tw, omth = 1.0f - th, omtd = 1.0f - td;

        // Consume corner pairs as they load: at most 2 float4 live at once.
        float4 r;
        {
            float c00x, c00y, c00z, c00w, c01x, c01y, c01z, c01w;
            {
                const float4 va = ib[(d0i * DV + h0i) * DV + w0i];
                const float4 vb = ib[(d0i * DV + h0i) * DV + w1i];
                c00x = va.x * omtw + vb.x * tw;  c00y = va.y * omtw + vb.y * tw;
                c00z = va.z * omtw + vb.z * tw;  c00w = va.w * omtw + vb.w * tw;
            }
            {
                const float4 va = ib[(d0i * DV + h1i) * DV + w0i];
                const float4 vb = ib[(d0i * DV + h1i) * DV + w1i];
                c01x = va.x * omtw + vb.x * tw;  c01y = va.y * omtw + vb.y * tw;
                c01z = va.z * omtw + vb.z * tw;  c01w = va.w * omtw + vb.w * tw;
            }
            const float c0x = c00x * omth + c01x * th;
            const float c0y = c00y * omth + c01y * th;
            const float c0z = c00z * omth + c01z * th;
            const float c0w = c00w * omth + c01w * th;

            float c10x, c10y, c10z, c10w, c11x, c11y, c11z, c11w;
            {
                const float4 va = ib[(d1i * DV + h0i) * DV + w0i];
                const float4 vb = ib[(d1i * DV + h0i) * DV + w1i];
                c10x = va.x * omtw + vb.x * tw;  c10y = va.y * omtw + vb.y * tw;
                c10z = va.z * omtw + vb.z * tw;  c10w = va.w * omtw + vb.w * tw;
            }
            {
                const float4 va = ib[(d1i * DV + h1i) * DV + w0i];
                const float4 vb = ib[(d1i * DV + h1i) * DV + w1i];
                c11x = va.x * omtw + vb.x * tw;  c11y = va.y * omtw + vb.y * tw;
                c11z = va.z * omtw + vb.z * tw;  c11w = va.w * omtw + vb.w * tw;
            }
            const float c1x = c10x * omth + c11x * th;
            const float c1y = c10y * omth + c11y * th;
            const float c1z = c10z * omth + c11z * th;
            const float c1w = c10w * omth + c11w * th;

            r.x = c0x * omtd + c1x * td;
            r.y = c0y * omtd + c1y * td;
            r.z = c0z * omtd + c1z * td;
            r.w = c0w * omtd + c1w * td;
        }

        const int vox = ((b * DV + d) * DV + h) * DV + w;
        out_img[vox] = r;

        const int nd = min(max((int)rintf(wd), 0), DV - 1);
        const int nh = min(max((int)rintf(wh), 0), DV - 1);
        const int nw = min(max((int)rintf(ww), 0), DV - 1);
        const int lv = lab[(size_t)b * NVOX + (nd * DV + nh) * DV + nw];
        out_lab[vox] = (float)lv;

        __syncthreads();   // row[] reused next iteration
    }
}

extern "C" void kernel_launch(void* const* d_in, const int* in_sizes, int n_in,
                              void* d_out, int out_size) {
    const float4* img    = (const float4*)d_in[0];
    const int*    lab    = (const int*)d_in[1];
    const float*  coarse = (const float*)d_in[2];

    float* out   = (float*)d_out;
    float4* oimg = (float4*)out;
    float*  olab = out + (size_t)2 * IMG_FLOATS_PER_B;

    precompute_weights_kernel<<<1, 128>>>();
    { dim3 g(DV, 2);                 resizeDH_kernel<<<g, 128>>>(coarse); }
    { dim3 g(DV, DV / D_CHUNK, 2);   resizeW_gaussD_kernel<<<g, 128>>>(); }
    { dim3 g(DV / H_TILE, DV, 2);    warp_fused_kernel<<<g, 128>>>(img, lab, oimg, olab); }
}